// round 12
// baseline (speedup 1.0000x reference)
#include <cuda_runtime.h>
#include <cuda_bf16.h>

#define TICKS   1000
#define TPAD    1024        // TICKS rounded up to 32 — sim chunks read the pad
#define NTAPS   49
#define KW      7
#define OUT_CH  128
#define MAXD    14          // 6 + min(stride,8)
#define MAXC    (MAXD*MAXD) // 196

// ---- scratch (no allocations allowed) ----
// Transposed layout: hist[cls][t] -> warp-coalesced loads over t in sim Phase B.
__device__ __align__(16) float d_hist[MAXC * TICKS];

__device__ __forceinline__ int imin(int a, int b) { return a < b ? a : b; }

// ------------------------------------------------------------------
// 1) event scatter into hist[cls][t].  (unchanged from R11 — ~6us)
// ------------------------------------------------------------------
__global__ void __launch_bounds__(1024) scatter_kernel(
    const int* __restrict__ tk, const int* __restrict__ xs,
    const int* __restrict__ ys, const float* __restrict__ vs,
    const int* __restrict__ sp, int n)
{
    __shared__ float sh[4 * 1024];             // [hot][t], t padded to 1024
    const int stride = *sp;
    const int D  = 6 + imin(stride, 8);
    const bool s2 = (stride == 2);

    if (s2) {
        for (int i = threadIdx.x; i < 4 * 1024; i += blockDim.x) sh[i] = 0.f;
        __syncthreads();
    }

    const int tid = blockIdx.x * blockDim.x + threadIdx.x;
    const int nth = gridDim.x * blockDim.x;

    auto proc = [&](int t, int x, int y, float v) {
        if (s2) {                                // warp-uniform branch
            if (x >= 6 && y >= 6) {              // hot: smem ATOMS
                int h = ((y & 1) << 1) | (x & 1);
                atomicAdd(&sh[h * 1024 + t], v);
            } else {                             // cold (~9%): global RED
                int cx = (x < 6) ? x : 6 + (x & 1);
                int cy = (y < 6) ? y : 6 + (y & 1);
                atomicAdd(&d_hist[(cy * 8 + cx) * TICKS + t], v);
            }
        } else {
            int cx = (x < 6) ? x : 6 + imin(x % stride, 7);
            int cy = (y < 6) ? y : 6 + imin(y % stride, 7);
            atomicAdd(&d_hist[(cy * D + cx) * TICKS + t], v);
        }
    };

    const int n4 = n >> 2;
    const int4*   t4 = reinterpret_cast<const int4*>(tk);
    const int4*   x4 = reinterpret_cast<const int4*>(xs);
    const int4*   y4 = reinterpret_cast<const int4*>(ys);
    const float4* v4 = reinterpret_cast<const float4*>(vs);

    for (int i = tid; i < n4; i += nth) {
        int4   a = t4[i];
        int4   b = x4[i];
        int4   c = y4[i];
        float4 w = v4[i];
        proc(a.x, b.x, c.x, w.x);
        proc(a.y, b.y, c.y, w.y);
        proc(a.z, b.z, c.z, w.z);
        proc(a.w, b.w, c.w, w.w);
    }
    for (int i = (n4 << 2) + tid; i < n; i += nth)
        proc(tk[i], xs[i], ys[i], vs[i]);

    if (s2) {
        __syncthreads();
        // flush hot classes: stride=2 -> D=8, cls = (6+ry)*8 + (6+rx) = 54+8ry+rx
        for (int i = threadIdx.x; i < 4 * TICKS; i += blockDim.x) {
            int h = i / TICKS, t = i - h * TICKS;
            float val = sh[h * 1024 + t];
            if (val != 0.f) {
                int cls = 54 + 8 * (h >> 1) + (h & 1);
                atomicAdd(&d_hist[cls * TICKS + t], val);
            }
        }
    }
}

// ------------------------------------------------------------------
// 2) fused drive + Izhikevich sim — TWO channels per CTA (64 CTAs).
//    Phase C runs two independent recurrences interleaved in one warp:
//    channel B's instructions issue inside channel A's chain-stall
//    bubbles (R11 post-mortem: ~36cyc chain, ~50cyc measured -> slack).
//    Per-channel arithmetic/order identical to R11 -> bit-identical.
// ------------------------------------------------------------------
__global__ void __launch_bounds__(1024) sim_kernel(
    const float* __restrict__ w, const int* __restrict__ sp,
    float* __restrict__ out)
{
    __shared__ float wc0[MAXC], wc1[MAXC];
    __shared__ float sg0[TPAD + 4], sg1[TPAD + 4];

    const int c0  = blockIdx.x * 2;
    const int c1  = c0 + 1;
    const int tid = threadIdx.x;
    const int stride = *sp;
    const int D = 6 + imin(stride, 8);
    const int C = D * D;

    // ---- Phase A: class weights for both channels ----
    // threads [0,C): channel 0;  threads [512, 512+C): channel 1
    if (tid < C || (tid >= 512 && tid < 512 + C)) {
        const int ch  = (tid >= 512);
        const int cls = ch ? tid - 512 : tid;
        const int cc  = ch ? c1 : c0;
        const int cy = cls / D, cx = cls % D;
        int sx, lx, sy, ly;
        if (cx < 6) { sx = cx % stride; lx = cx; } else { sx = cx - 6; lx = 6; }
        if (cy < 6) { sy = cy % stride; ly = cy; } else { sy = cy - 6; ly = 6; }
        float acc = 0.f;
        for (int ky = sy; ky <= ly; ky += stride)
            for (int kx = sx; kx <= lx; kx += stride)
                acc += w[cc * NTAPS + ky * KW + kx];
        if (ch) wc1[cls] = acc; else wc0[cls] = acc;
    }
    // zero sg pads (Phase B overwrites [1..TICKS])
    for (int i = tid; i < TPAD + 4; i += blockDim.x) { sg0[i] = 0.f; sg1[i] = 0.f; }
    __syncthreads();

    // ---- Phase B: sg[t] = dot(wc, hist[:, t-1]); each hist load feeds both ----
    if (tid >= 1 && tid <= TICKS) {
        const int tm1 = tid - 1;                  // source tick
        const float* __restrict__ hp = d_hist + tm1;
        float a0 = 0.f, a1 = 0.f;
        #pragma unroll 16
        for (int cls = 0; cls < C; ++cls) {
            float hv = __ldg(&hp[cls * TICKS]);
            a0 = fmaf(wc0[cls], hv, a0);
            a1 = fmaf(wc1[cls], hv, a1);
        }
        sg0[tid] = a0;                            // 1-tick synaptic delay
        sg1[tid] = a1;
    }
    __syncthreads();

    // ---- Phase C: serial sim, warp 0, two interleaved recurrences ----
    if (tid >= 32) return;
    const int lane = tid;

    float* __restrict__ ospk0 = out + c0 * TICKS;
    float* __restrict__ ovtr0 = out + OUT_CH * TICKS + c0 * TICKS;
    float* __restrict__ ospk1 = out + c1 * TICKS;
    float* __restrict__ ovtr1 = out + OUT_CH * TICKS + c1 * TICKS;

    const float decay = 0.9f;                        // 1 - dt/tau_fall
    const float h     = (float)(0.001 / 150.0);      // dt / C
    const float Kp = 1.2f, VR = -75.f, VT = -45.f;
    const float AP = 0.01f, BP = 5.f, VP = 50.f;
    const float DP = 130.f, VRS = -56.f, IIN = 350.f, DT = 0.001f;
    // constant-folded spike-path product (same RN rounding; exact operands)
    const float QC = 1.2f * (VRS - VR) * (VRS - VT);

    float vA = VR, uA = 0.f, SA = 0.f;  bool pA = false;
    float vB = VR, uB = 0.f, SB = 0.f;  bool pB = false;

    for (int t0 = 0; t0 < TICKS; t0 += 32) {
        float kv0 = 0.f, ks0 = 0.f, kv1 = 0.f, ks1 = 0.f;
        #pragma unroll
        for (int i = 0; i < 32; ++i) {
            // ---- channel A ----
            float gtA = sg0[t0 + i];
            SA = SA * decay + gtA;
            float IA = IIN + SA;
            float vnA  = vA + (Kp * (vA - VR) * (vA - VT) - uA + IA) * h;
            float vspA = VRS + (QC - uA + IA) * h;
            float vwA  = pA ? vspA : vnA;            // FSEL (pred ready)
            float unA  = uA + AP * (BP * (vwA - VR) - uA) * DT;
            bool  sA   = vwA >= VP;
            float sfA  = sA ? 1.f : 0.f;
            float vpA  = sA ? VRS : vwA;
            uA = sA ? unA + DP : unA;
            vA = vwA; pA = sA;
            kv0 = (lane == i) ? vpA : kv0;
            ks0 = (lane == i) ? sfA : ks0;
            // ---- channel B (independent chain fills A's stall bubbles) ----
            float gtB = sg1[t0 + i];
            SB = SB * decay + gtB;
            float IB = IIN + SB;
            float vnB  = vB + (Kp * (vB - VR) * (vB - VT) - uB + IB) * h;
            float vspB = VRS + (QC - uB + IB) * h;
            float vwB  = pB ? vspB : vnB;
            float unB  = uB + AP * (BP * (vwB - VR) - uB) * DT;
            bool  sB   = vwB >= VP;
            float sfB  = sB ? 1.f : 0.f;
            float vpB  = sB ? VRS : vwB;
            uB = sB ? unB + DP : unB;
            vB = vwB; pB = sB;
            kv1 = (lane == i) ? vpB : kv1;
            ks1 = (lane == i) ? sfB : ks1;
        }
        int t = t0 + lane;
        if (t < TICKS) {                             // guard: 1000 % 32 != 0
            ospk0[t] = ks0;  ovtr0[t] = kv0;         // coalesced per chunk
            ospk1[t] = ks1;  ovtr1[t] = kv1;
        }
    }
}

// ------------------------------------------------------------------
extern "C" void kernel_launch(void* const* d_in, const int* in_sizes, int n_in,
                              void* d_out, int out_size)
{
    const int*   tk = (const int*)  d_in[0];   // spike_ticks
    const int*   xs = (const int*)  d_in[1];   // spike_x
    const int*   ys = (const int*)  d_in[2];   // spike_y
    const float* vs = (const float*)d_in[3];   // spike_values
    const float* w  = (const float*)d_in[4];   // weights [128,49]
    const int*   sp = (const int*)  d_in[5];   // stride
    const int    n  = in_sizes[0];

    void* hist_ptr = nullptr;
    cudaGetSymbolAddress(&hist_ptr, d_hist);
    cudaMemsetAsync(hist_ptr, 0, sizeof(float) * MAXC * TICKS);   // memset node

    scatter_kernel<<<148, 1024>>>(tk, xs, ys, vs, sp, n);
    sim_kernel<<<OUT_CH / 2, 1024>>>(w, sp, (float*)d_out);
}

// round 13
// speedup vs baseline: 1.2829x; 1.2829x over previous
#include <cuda_runtime.h>
#include <cuda_bf16.h>

#define TICKS   1000
#define TPAD    1024        // TICKS rounded up to 32 — sim chunks read the pad
#define NTAPS   49
#define KW      7
#define OUT_CH  128
#define MAXD    14          // 6 + min(stride,8)
#define MAXC    (MAXD*MAXD) // 196

// ---- scratch (no allocations allowed) ----
// Transposed layout: hist[cls][t] -> warp-coalesced loads over t in sim Phase B.
__device__ __align__(16) float d_hist[MAXC * TICKS];

__device__ __forceinline__ int imin(int a, int b) { return a < b ? a : b; }

// ------------------------------------------------------------------
// 1) event scatter into hist[cls][t].
//    stride==2 fast path: the 4 hot classes (x>=6 && y>=6, 91% of events)
//    aggregate in shared memory (ATOMS), flushed once per CTA. Cold events
//    + generic strides go straight to L2 via RED.F32 (no return -> no
//    scoreboard stalls). spike_values are 1.0f so per-slot sums are exact
//    integers: atomic ordering cannot perturb results.
// ------------------------------------------------------------------
__global__ void __launch_bounds__(1024) scatter_kernel(
    const int* __restrict__ tk, const int* __restrict__ xs,
    const int* __restrict__ ys, const float* __restrict__ vs,
    const int* __restrict__ sp, int n)
{
    __shared__ float sh[4 * 1024];             // [hot][t], t padded to 1024
    const int stride = *sp;
    const int D  = 6 + imin(stride, 8);
    const bool s2 = (stride == 2);

    if (s2) {
        for (int i = threadIdx.x; i < 4 * 1024; i += blockDim.x) sh[i] = 0.f;
        __syncthreads();
    }

    const int tid = blockIdx.x * blockDim.x + threadIdx.x;
    const int nth = gridDim.x * blockDim.x;

    auto proc = [&](int t, int x, int y, float v) {
        if (s2) {                                // warp-uniform branch
            if (x >= 6 && y >= 6) {              // hot: smem ATOMS
                int h = ((y & 1) << 1) | (x & 1);
                atomicAdd(&sh[h * 1024 + t], v);
            } else {                             // cold (~9%): global RED
                int cx = (x < 6) ? x : 6 + (x & 1);
                int cy = (y < 6) ? y : 6 + (y & 1);
                atomicAdd(&d_hist[(cy * 8 + cx) * TICKS + t], v);
            }
        } else {
            int cx = (x < 6) ? x : 6 + imin(x % stride, 7);
            int cy = (y < 6) ? y : 6 + imin(y % stride, 7);
            atomicAdd(&d_hist[(cy * D + cx) * TICKS + t], v);
        }
    };

    const int n4 = n >> 2;
    const int4*   t4 = reinterpret_cast<const int4*>(tk);
    const int4*   x4 = reinterpret_cast<const int4*>(xs);
    const int4*   y4 = reinterpret_cast<const int4*>(ys);
    const float4* v4 = reinterpret_cast<const float4*>(vs);

    for (int i = tid; i < n4; i += nth) {
        int4   a = t4[i];
        int4   b = x4[i];
        int4   c = y4[i];
        float4 w = v4[i];
        proc(a.x, b.x, c.x, w.x);
        proc(a.y, b.y, c.y, w.y);
        proc(a.z, b.z, c.z, w.z);
        proc(a.w, b.w, c.w, w.w);
    }
    for (int i = (n4 << 2) + tid; i < n; i += nth)
        proc(tk[i], xs[i], ys[i], vs[i]);

    if (s2) {
        __syncthreads();
        // flush hot classes: stride=2 -> D=8, cls = (6+ry)*8 + (6+rx) = 54+8ry+rx
        for (int i = threadIdx.x; i < 4 * TICKS; i += blockDim.x) {
            int h = i / TICKS, t = i - h * TICKS;
            float val = sh[h * 1024 + t];
            if (val != 0.f) {
                int cls = 54 + 8 * (h >> 1) + (h & 1);
                atomicAdd(&d_hist[cls * TICKS + t], val);
            }
        }
    }
}

// ------------------------------------------------------------------
// 2) fused drive + Izhikevich sim. One 1024-thread block per channel
//    (reverted to the R9/R11 single-channel shape — R12's two-channel
//    interleave made the single warp issue-bound and regressed).
//    Phase C chain fix: u's spike increment folded into ONE FADD with a
//    pre-selected operand (sp ? DP : 0.0f). The DP/0 select resolves in
//    parallel with unew, cutting the binding u-path by ~5cyc/tick.
//    unew+0.0f == unew exactly (u is never -0), spiked path is the
//    identical unew+DP FADD -> bit-identical output.
// ------------------------------------------------------------------
__global__ void __launch_bounds__(1024) sim_kernel(
    const float* __restrict__ w, const int* __restrict__ sp,
    float* __restrict__ out)
{
    __shared__ float wc[MAXC];
    __shared__ float sg[TPAD + 4];

    const int c   = blockIdx.x;
    const int tid = threadIdx.x;
    const int stride = *sp;
    const int D = 6 + imin(stride, 8);
    const int C = D * D;

    // ---- Phase A: class weights for this channel ----
    if (tid < C) {
        const int cls = tid;
        const int cy = cls / D, cx = cls % D;
        int sx, lx, sy, ly;
        if (cx < 6) { sx = cx % stride; lx = cx; } else { sx = cx - 6; lx = 6; }
        if (cy < 6) { sy = cy % stride; ly = cy; } else { sy = cy - 6; ly = 6; }
        float acc = 0.f;
        for (int ky = sy; ky <= ly; ky += stride)
            for (int kx = sx; kx <= lx; kx += stride)
                acc += w[c * NTAPS + ky * KW + kx];
        wc[cls] = acc;
    }
    // zero sg (covers sg[0] and the pad)
    for (int i = tid; i < TPAD + 4; i += blockDim.x) sg[i] = 0.f;
    __syncthreads();

    // ---- Phase B: sg[t] = dot(wc, hist[:, t-1]) for t in [1, TICKS] ----
    if (tid >= 1 && tid <= TICKS) {
        const int tm1 = tid - 1;                  // source tick
        const float* __restrict__ hp = d_hist + tm1;
        float acc = 0.f;
        #pragma unroll 16
        for (int cls = 0; cls < C; ++cls)
            acc = fmaf(wc[cls], __ldg(&hp[cls * TICKS]), acc);
        sg[tid] = acc;                            // 1-tick synaptic delay
    }
    __syncthreads();

    // ---- Phase C: serial sim, warp 0 only ----
    if (tid >= 32) return;
    const int lane = tid;

    float* __restrict__ ospk = out + c * TICKS;
    float* __restrict__ ovtr = out + OUT_CH * TICKS + c * TICKS;

    const float decay = 0.9f;                        // 1 - dt/tau_fall
    const float h     = (float)(0.001 / 150.0);      // dt / C
    const float Kp = 1.2f, VR = -75.f, VT = -45.f;
    const float AP = 0.01f, BP = 5.f, VP = 50.f;
    const float DP = 130.f, VRS = -56.f, IIN = 350.f, DT = 0.001f;
    // constant-folded spike-path product: Kp*(VRS-VR)*(VRS-VT), same RN
    // rounding the runtime FADD/FMULs produce (19 and -11 are exact).
    const float QC = 1.2f * (VRS - VR) * (VRS - VT);

    // carry: vpre = v BEFORE reset of previous tick; spprev = its spike bit.
    float vpre = VR, u = 0.f, S = 0.f;
    bool  spprev = false;

    for (int t0 = 0; t0 < TICKS; t0 += 32) {
        float keepv = 0.f, keeps = 0.f;
        #pragma unroll
        for (int i = 0; i < 32; ++i) {
            float gt = sg[t0 + i];                   // pad ticks harmless
            S = S * decay + gt;                      // summed synapse state
            float I = IIN + S;                       // I_bias = 0
            // both candidates, computed before spprev's select:
            float vn  = vpre + (Kp * (vpre - VR) * (vpre - VT) - u + I) * h;
            float vsp = VRS  + (QC - u + I) * h;     // chains via u,I only
            float vnew = spprev ? vsp : vn;          // FSEL (pred-as-data)
            // u update uses pre-reset v (reference order)
            float unew = u + AP * (BP * (vnew - VR) - u) * DT;
            bool sp_ = vnew >= VP;
            float spf   = sp_ ? 1.f : 0.f;
            float vpost = sp_ ? VRS : vnew;          // output value only
            float dpadd = sp_ ? DP  : 0.0f;          // select runs parallel
            u = unew + dpadd;                        // ONE FADD on u-path
            vpre = vnew; spprev = sp_;
            keepv = (lane == i) ? vpost : keepv;     // register-keep, off chain
            keeps = (lane == i) ? spf   : keeps;
        }
        int t = t0 + lane;
        if (t < TICKS) {                             // guard: 1000 % 32 != 0
            ospk[t] = keeps;                         // coalesced per chunk
            ovtr[t] = keepv;
        }
    }
}

// ------------------------------------------------------------------
extern "C" void kernel_launch(void* const* d_in, const int* in_sizes, int n_in,
                              void* d_out, int out_size)
{
    const int*   tk = (const int*)  d_in[0];   // spike_ticks
    const int*   xs = (const int*)  d_in[1];   // spike_x
    const int*   ys = (const int*)  d_in[2];   // spike_y
    const float* vs = (const float*)d_in[3];   // spike_values
    const float* w  = (const float*)d_in[4];   // weights [128,49]
    const int*   sp = (const int*)  d_in[5];   // stride
    const int    n  = in_sizes[0];

    void* hist_ptr = nullptr;
    cudaGetSymbolAddress(&hist_ptr, d_hist);
    cudaMemsetAsync(hist_ptr, 0, sizeof(float) * MAXC * TICKS);   // memset node

    scatter_kernel<<<148, 1024>>>(tk, xs, ys, vs, sp, n);
    sim_kernel<<<OUT_CH, 1024>>>(w, sp, (float*)d_out);
}

// round 14
// speedup vs baseline: 1.4814x; 1.1547x over previous
#include <cuda_runtime.h>
#include <cuda_bf16.h>

#define TICKS   1000
#define TPAD    1024        // TICKS rounded up to 32 — sim chunks read the pad
#define NTAPS   49
#define KW      7
#define OUT_CH  128
#define MAXD    14          // 6 + min(stride,8)
#define MAXC    (MAXD*MAXD) // 196

// ---- scratch (no allocations allowed) ----
__device__ __align__(16) float d_hist[MAXC * TICKS];   // hist[cls][t]

__device__ __forceinline__ int imin(int a, int b) { return a < b ? a : b; }

// ------------------------------------------------------------------
// 1) event scatter into hist[cls][t]. (unchanged — ~5us)
// ------------------------------------------------------------------
__global__ void __launch_bounds__(1024) scatter_kernel(
    const int* __restrict__ tk, const int* __restrict__ xs,
    const int* __restrict__ ys, const float* __restrict__ vs,
    const int* __restrict__ sp, int n)
{
    __shared__ float sh[4 * 1024];             // [hot][t], t padded to 1024
    const int stride = *sp;
    const int D  = 6 + imin(stride, 8);
    const bool s2 = (stride == 2);

    if (s2) {
        for (int i = threadIdx.x; i < 4 * 1024; i += blockDim.x) sh[i] = 0.f;
        __syncthreads();
    }

    const int tid = blockIdx.x * blockDim.x + threadIdx.x;
    const int nth = gridDim.x * blockDim.x;

    auto proc = [&](int t, int x, int y, float v) {
        if (s2) {
            if (x >= 6 && y >= 6) {              // hot: smem ATOMS
                int h = ((y & 1) << 1) | (x & 1);
                atomicAdd(&sh[h * 1024 + t], v);
            } else {                             // cold (~9%): global RED
                int cx = (x < 6) ? x : 6 + (x & 1);
                int cy = (y < 6) ? y : 6 + (y & 1);
                atomicAdd(&d_hist[(cy * 8 + cx) * TICKS + t], v);
            }
        } else {
            int cx = (x < 6) ? x : 6 + imin(x % stride, 7);
            int cy = (y < 6) ? y : 6 + imin(y % stride, 7);
            atomicAdd(&d_hist[(cy * D + cx) * TICKS + t], v);
        }
    };

    const int n4 = n >> 2;
    const int4*   t4 = reinterpret_cast<const int4*>(tk);
    const int4*   x4 = reinterpret_cast<const int4*>(xs);
    const int4*   y4 = reinterpret_cast<const int4*>(ys);
    const float4* v4 = reinterpret_cast<const float4*>(vs);

    for (int i = tid; i < n4; i += nth) {
        int4   a = t4[i];
        int4   b = x4[i];
        int4   c = y4[i];
        float4 w = v4[i];
        proc(a.x, b.x, c.x, w.x);
        proc(a.y, b.y, c.y, w.y);
        proc(a.z, b.z, c.z, w.z);
        proc(a.w, b.w, c.w, w.w);
    }
    for (int i = (n4 << 2) + tid; i < n; i += nth)
        proc(tk[i], xs[i], ys[i], vs[i]);

    if (s2) {
        __syncthreads();
        for (int i = threadIdx.x; i < 4 * TICKS; i += blockDim.x) {
            int h = i / TICKS, t = i - h * TICKS;
            float val = sh[h * 1024 + t];
            if (val != 0.f) {
                int cls = 54 + 8 * (h >> 1) + (h & 1);
                atomicAdd(&d_hist[cls * TICKS + t], val);
            }
        }
    }
}

// ------------------------------------------------------------------
// 2) fused drive + Izhikevich sim. One 1024-thread block per channel.
//    Phase C REFORMULATED (mathematically equivalent, minimal depth):
//      vnew = fmaf(-h, u, pprev ? dsp : r2)
//        r2  = fmaf(Kp*h*(v-VR), (v-VT), v + I*h)      [u-free]
//        dsp = fmaf(QC + I, h, VRS)                     [u-free]
//      u    = fmaf(AP*BP*DT, vnew-VR, u*(1-AP*DT)) (+DP if spiked)
//    Chain = 25cyc/tick (was ~53). Rounding deltas ~1e-7 rel — the
//    fmad-contracted "exact" version already deviated from JAX at this
//    scale (rel_err 8e-8) with zero spike flips, so this is in-margin.
// ------------------------------------------------------------------
__global__ void __launch_bounds__(1024) sim_kernel(
    const float* __restrict__ w, const int* __restrict__ sp,
    float* __restrict__ out)
{
    __shared__ float wc[MAXC];
    __shared__ float sg[TPAD + 4];

    const int c   = blockIdx.x;
    const int tid = threadIdx.x;
    const int stride = *sp;
    const int D = 6 + imin(stride, 8);
    const int C = D * D;

    // ---- Phase A: class weights for this channel ----
    if (tid < C) {
        const int cls = tid;
        const int cy = cls / D, cx = cls % D;
        int sx, lx, sy, ly;
        if (cx < 6) { sx = cx % stride; lx = cx; } else { sx = cx - 6; lx = 6; }
        if (cy < 6) { sy = cy % stride; ly = cy; } else { sy = cy - 6; ly = 6; }
        float acc = 0.f;
        for (int ky = sy; ky <= ly; ky += stride)
            for (int kx = sx; kx <= lx; kx += stride)
                acc += w[c * NTAPS + ky * KW + kx];
        wc[cls] = acc;
    }
    for (int i = tid; i < TPAD + 4; i += blockDim.x) sg[i] = 0.f;
    __syncthreads();

    // ---- Phase B: sg[t] = dot(wc, hist[:, t-1]) for t in [1, TICKS] ----
    if (tid >= 1 && tid <= TICKS) {
        const int tm1 = tid - 1;
        const float* __restrict__ hp = d_hist + tm1;
        float acc = 0.f;
        #pragma unroll 16
        for (int cls = 0; cls < C; ++cls)
            acc = fmaf(wc[cls], __ldg(&hp[cls * TICKS]), acc);
        sg[tid] = acc;                            // 1-tick synaptic delay
    }
    __syncthreads();

    // ---- Phase C: serial sim, warp 0 only ----
    if (tid >= 32) return;
    const int lane = tid;

    float* __restrict__ ospk = out + c * TICKS;
    float* __restrict__ ovtr = out + OUT_CH * TICKS + c * TICKS;

    const float decay = 0.9f;                        // 1 - dt/tau_fall
    const float h     = (float)(0.001 / 150.0);      // dt / C
    const float negh  = -h;
    const float Kp = 1.2f, VR = -75.f, VT = -45.f;
    const float AP = 0.01f, BP = 5.f, VP = 50.f;
    const float DP = 130.f, VRS = -56.f, IIN = 350.f, DT = 0.001f;
    const float QC  = 1.2f * (VRS - VR) * (VRS - VT); // spike-path quadratic
    const float Kph = Kp * h;                         // folded constants
    const float K1  = AP * BP * DT;                   // 5e-5
    const float K2  = 1.0f - AP * DT;                 // 1 - 1e-5

    float v = VR, u = 0.f, S = 0.f;
    bool  pprev = false;

    for (int t0 = 0; t0 < TICKS; t0 += 32) {
        float keepv = 0.f, keeps = 0.f;
        #pragma unroll
        for (int i = 0; i < 32; ++i) {
            float gt = sg[t0 + i];                   // pad ticks harmless
            // drive terms: fast serial S-chain, all off the v-loop
            S = S * decay + gt;
            float I   = IIN + S;
            float Ih  = I * h;
            float dsp = fmaf(QC + I, h, VRS);        // spike-path target
            // v-loop (25cyc): t1/t2 -> m2 -> r2 -> FSEL -> FFMA(-h*u)
            float t1  = v - VR;
            float t2  = v - VT;
            float m2  = Kph * t1;
            float vI  = v + Ih;                      // off-path
            float r2  = fmaf(m2, t2, vI);            // u-free candidate
            float sel = pprev ? dsp : r2;            // pred ready long ago
            float vnew = fmaf(negh, u, sel);
            // u-path (off the binding loop): u' = K1*(vnew-VR) + u*K2 (+DP)
            float uK2 = u * K2;                      // early
            float t1n = vnew - VR;
            float un  = fmaf(K1, t1n, uK2);
            bool  sp_ = vnew >= VP;
            float dpadd = sp_ ? DP : 0.0f;
            u = un + dpadd;
            float spf   = sp_ ? 1.f : 0.f;
            float vpost = sp_ ? VRS : vnew;          // recorded value
            v = vnew; pprev = sp_;
            keepv = (lane == i) ? vpost : keepv;
            keeps = (lane == i) ? spf   : keeps;
        }
        int t = t0 + lane;
        if (t < TICKS) {                             // guard: 1000 % 32 != 0
            ospk[t] = keeps;
            ovtr[t] = keepv;
        }
    }
}

// ------------------------------------------------------------------
extern "C" void kernel_launch(void* const* d_in, const int* in_sizes, int n_in,
                              void* d_out, int out_size)
{
    const int*   tk = (const int*)  d_in[0];   // spike_ticks
    const int*   xs = (const int*)  d_in[1];   // spike_x
    const int*   ys = (const int*)  d_in[2];   // spike_y
    const float* vs = (const float*)d_in[3];   // spike_values
    const float* w  = (const float*)d_in[4];   // weights [128,49]
    const int*   sp = (const int*)  d_in[5];   // stride
    const int    n  = in_sizes[0];

    void* hist_ptr = nullptr;
    cudaGetSymbolAddress(&hist_ptr, d_hist);
    cudaMemsetAsync(hist_ptr, 0, sizeof(float) * MAXC * TICKS);   // memset node

    scatter_kernel<<<148, 1024>>>(tk, xs, ys, vs, sp, n);
    sim_kernel<<<OUT_CH, 1024>>>(w, sp, (float*)d_out);
}

// round 15
// speedup vs baseline: 1.4913x; 1.0067x over previous
#include <cuda_runtime.h>
#include <cuda_bf16.h>

#define TICKS   1000
#define TPAD    1024        // TICKS rounded up to 32 — sim chunks read the pad
#define NTAPS   49
#define KW      7
#define OUT_CH  128
#define MAXD    14          // 6 + min(stride,8)
#define MAXC    (MAXD*MAXD) // 196

// ---- scratch (no allocations allowed) ----
__device__ __align__(16) float d_hist[MAXC * TICKS];   // hist[cls][t]

__device__ __forceinline__ int imin(int a, int b) { return a < b ? a : b; }

// ------------------------------------------------------------------
// 1) event scatter into hist[cls][t]. (unchanged — ~5us)
// ------------------------------------------------------------------
__global__ void __launch_bounds__(1024) scatter_kernel(
    const int* __restrict__ tk, const int* __restrict__ xs,
    const int* __restrict__ ys, const float* __restrict__ vs,
    const int* __restrict__ sp, int n)
{
    __shared__ float sh[4 * 1024];             // [hot][t], t padded to 1024
    const int stride = *sp;
    const int D  = 6 + imin(stride, 8);
    const bool s2 = (stride == 2);

    if (s2) {
        for (int i = threadIdx.x; i < 4 * 1024; i += blockDim.x) sh[i] = 0.f;
        __syncthreads();
    }

    const int tid = blockIdx.x * blockDim.x + threadIdx.x;
    const int nth = gridDim.x * blockDim.x;

    auto proc = [&](int t, int x, int y, float v) {
        if (s2) {
            if (x >= 6 && y >= 6) {              // hot: smem ATOMS
                int h = ((y & 1) << 1) | (x & 1);
                atomicAdd(&sh[h * 1024 + t], v);
            } else {                             // cold (~9%): global RED
                int cx = (x < 6) ? x : 6 + (x & 1);
                int cy = (y < 6) ? y : 6 + (y & 1);
                atomicAdd(&d_hist[(cy * 8 + cx) * TICKS + t], v);
            }
        } else {
            int cx = (x < 6) ? x : 6 + imin(x % stride, 7);
            int cy = (y < 6) ? y : 6 + imin(y % stride, 7);
            atomicAdd(&d_hist[(cy * D + cx) * TICKS + t], v);
        }
    };

    const int n4 = n >> 2;
    const int4*   t4 = reinterpret_cast<const int4*>(tk);
    const int4*   x4 = reinterpret_cast<const int4*>(xs);
    const int4*   y4 = reinterpret_cast<const int4*>(ys);
    const float4* v4 = reinterpret_cast<const float4*>(vs);

    for (int i = tid; i < n4; i += nth) {
        int4   a = t4[i];
        int4   b = x4[i];
        int4   c = y4[i];
        float4 w = v4[i];
        proc(a.x, b.x, c.x, w.x);
        proc(a.y, b.y, c.y, w.y);
        proc(a.z, b.z, c.z, w.z);
        proc(a.w, b.w, c.w, w.w);
    }
    for (int i = (n4 << 2) + tid; i < n; i += nth)
        proc(tk[i], xs[i], ys[i], vs[i]);

    if (s2) {
        __syncthreads();
        for (int i = threadIdx.x; i < 4 * TICKS; i += blockDim.x) {
            int h = i / TICKS, t = i - h * TICKS;
            float val = sh[h * 1024 + t];
            if (val != 0.f) {
                int cls = 54 + 8 * (h >> 1) + (h & 1);
                atomicAdd(&d_hist[cls * TICKS + t], val);
            }
        }
    }
}

// ------------------------------------------------------------------
// 2) fused drive + Izhikevich sim. One 1024-thread block per channel.
//    Phase C: drive joins on the U-SIDE (R14 post-mortem: joining at
//    vI put the S->I->Ih chain on the v-loop, 40cyc/tick). Algebra:
//      vnew = (pprev ? DSPQ : rq) + huIh
//        rq   = fmaf(Kph*(v-VR), (v-VT), v)   [drive-free, u-free]
//        DSPQ = VRS + QC*h                     [constant]
//        huIh = fmaf(-h, u, Ih)                [u-path, has slack]
//      Ih = fmaf(S, h, IIN*h);  S = fmaf(S, decay, g)  [fast chain,
//        independent of v/u -> runs ahead, absorbs LDS latency]
//    Binding chain: t1 -> m2 -> rq -> FSEL -> FADD = 25cyc/tick.
// ------------------------------------------------------------------
__global__ void __launch_bounds__(1024) sim_kernel(
    const float* __restrict__ w, const int* __restrict__ sp,
    float* __restrict__ out)
{
    __shared__ float wc[MAXC];
    __shared__ float sg[TPAD + 4];

    const int c   = blockIdx.x;
    const int tid = threadIdx.x;
    const int stride = *sp;
    const int D = 6 + imin(stride, 8);
    const int C = D * D;

    // ---- Phase A: class weights for this channel ----
    if (tid < C) {
        const int cls = tid;
        const int cy = cls / D, cx = cls % D;
        int sx, lx, sy, ly;
        if (cx < 6) { sx = cx % stride; lx = cx; } else { sx = cx - 6; lx = 6; }
        if (cy < 6) { sy = cy % stride; ly = cy; } else { sy = cy - 6; ly = 6; }
        float acc = 0.f;
        for (int ky = sy; ky <= ly; ky += stride)
            for (int kx = sx; kx <= lx; kx += stride)
                acc += w[c * NTAPS + ky * KW + kx];
        wc[cls] = acc;
    }
    for (int i = tid; i < TPAD + 4; i += blockDim.x) sg[i] = 0.f;
    __syncthreads();

    // ---- Phase B: sg[t] = dot(wc, hist[:, t-1]) for t in [1, TICKS] ----
    if (tid >= 1 && tid <= TICKS) {
        const int tm1 = tid - 1;
        const float* __restrict__ hp = d_hist + tm1;
        float acc = 0.f;
        #pragma unroll 16
        for (int cls = 0; cls < C; ++cls)
            acc = fmaf(wc[cls], __ldg(&hp[cls * TICKS]), acc);
        sg[tid] = acc;                            // 1-tick synaptic delay
    }
    __syncthreads();

    // ---- Phase C: serial sim, warp 0 only ----
    if (tid >= 32) return;
    const int lane = tid;

    float* __restrict__ ospk = out + c * TICKS;
    float* __restrict__ ovtr = out + OUT_CH * TICKS + c * TICKS;

    const float decay = 0.9f;                        // 1 - dt/tau_fall
    const float h     = (float)(0.001 / 150.0);      // dt / C
    const float negh  = -h;
    const float Kp = 1.2f, VR = -75.f, VT = -45.f;
    const float AP = 0.01f, BP = 5.f, VP = 50.f;
    const float DP = 130.f, VRS = -56.f, IIN = 350.f, DT = 0.001f;
    const float QC   = 1.2f * (VRS - VR) * (VRS - VT);
    const float Kph  = Kp * h;
    const float K1   = AP * BP * DT;                 // 5e-5
    const float K2   = 1.0f - AP * DT;               // 1 - 1e-5
    const float IINh = IIN * h;
    const float DSPQ = VRS + QC * h;                 // constant spike base

    float v = VR, u = 0.f, S = 0.f;
    bool  pprev = false;

    for (int t0 = 0; t0 < TICKS; t0 += 32) {
        float keepv = 0.f, keeps = 0.f;
        #pragma unroll
        for (int i = 0; i < 32; ++i) {
            // drive chain (independent of v,u — scheduler runs it ahead)
            float gt = sg[t0 + i];                   // pad ticks harmless
            S = fmaf(S, decay, gt);                  // S*decay + g
            float Ih  = fmaf(S, h, IINh);            // (IIN+S)*h
            // u-side join: huIh = Ih - h*u  (u ready prev+15, this @+20)
            float huIh = fmaf(negh, u, Ih);
            // v-loop (25cyc): t1 -> m2 -> rq -> FSEL -> FADD
            float t1 = v - VR;
            float t2 = v - VT;
            float m2 = Kph * t1;
            float rq = fmaf(m2, t2, v);              // drive-free candidate
            float selq = pprev ? DSPQ : rq;          // pred resolved long ago
            float vnew = selq + huIh;
            // u-path (off the binding loop)
            float uK2 = u * K2;
            float t1n = vnew - VR;
            float un  = fmaf(K1, t1n, uK2);
            bool  sp_ = vnew >= VP;
            float dpadd = sp_ ? DP : 0.0f;
            u = un + dpadd;
            float spf   = sp_ ? 1.f : 0.f;
            float vpost = sp_ ? VRS : vnew;          // recorded value
            v = vnew; pprev = sp_;
            keepv = (lane == i) ? vpost : keepv;
            keeps = (lane == i) ? spf   : keeps;
        }
        int t = t0 + lane;
        if (t < TICKS) {                             // guard: 1000 % 32 != 0
            ospk[t] = keeps;
            ovtr[t] = keepv;
        }
    }
}

// ------------------------------------------------------------------
extern "C" void kernel_launch(void* const* d_in, const int* in_sizes, int n_in,
                              void* d_out, int out_size)
{
    const int*   tk = (const int*)  d_in[0];   // spike_ticks
    const int*   xs = (const int*)  d_in[1];   // spike_x
    const int*   ys = (const int*)  d_in[2];   // spike_y
    const float* vs = (const float*)d_in[3];   // spike_values
    const float* w  = (const float*)d_in[4];   // weights [128,49]
    const int*   sp = (const int*)  d_in[5];   // stride
    const int    n  = in_sizes[0];

    void* hist_ptr = nullptr;
    cudaGetSymbolAddress(&hist_ptr, d_hist);
    cudaMemsetAsync(hist_ptr, 0, sizeof(float) * MAXC * TICKS);   // memset node

    scatter_kernel<<<148, 1024>>>(tk, xs, ys, vs, sp, n);
    sim_kernel<<<OUT_CH, 1024>>>(w, sp, (float*)d_out);
}